// round 9
// baseline (speedup 1.0000x reference)
#include <cuda_runtime.h>
#include <cstdint>

#define S 4096
#define MAXLEN 50
#define NATT 64

// ---------------- scratch ----------------
__device__ float g_G[2 * S * 300];
__device__ float g_WTenc[2 * 256 * 300];
__device__ float g_WAT[200 * 400];
__device__ float g_enc[S * 200];
__device__ float g_kp[S * 200];             // kp row-major [i][k]
__device__ float g_vp[S * 200];             // vp row-major [i][g]
__device__ float g_QL[1000 * 200];          // Wq[:,100:200] @ L_tab[i]
__device__ float g_GL[1000 * 300];          // dec_Wih[:,100:200] @ L_tab[i]
__device__ float g_gihd0[300];              // dec_Wih[:,100:200] @ sent
__device__ float g_q[200];
__device__ float g_pm[NATT];
__device__ float g_pz[NATT];
__device__ float g_pv[NATT * 200];
__device__ unsigned g_cnt1[MAXLEN];
__device__ unsigned g_qflag[MAXLEN + 1];

__device__ __forceinline__ float tanhapx(float x) {
    float y; asm("tanh.approx.f32 %0, %1;" : "=f"(y) : "f"(x)); return y;
}
__device__ __forceinline__ float sigapx(float x) {
    return 0.5f + 0.5f * tanhapx(0.5f * x);
}
__device__ __forceinline__ unsigned vld(const unsigned* p) {
    return *(volatile const unsigned*)p;
}
__device__ __forceinline__ float warp_sum(float a) {
#pragma unroll
    for (int o = 16; o; o >>= 1) a += __shfl_xor_sync(0xffffffffu, a, o);
    return a;
}
__device__ __forceinline__ float warp_max(float a) {
#pragma unroll
    for (int o = 16; o; o >>= 1) a = fmaxf(a, __shfl_xor_sync(0xffffffffu, a, o));
    return a;
}
__device__ __forceinline__ float red8(float a) {
    a += __shfl_xor_sync(0xffffffffu, a, 4);
    a += __shfl_xor_sync(0xffffffffu, a, 2);
    a += __shfl_xor_sync(0xffffffffu, a, 1);
    return a;
}

// ---------------- K_transp ----------------
__global__ void k_transp(const float* fWih, const float* bWih, const float* attW) {
    int region = blockIdx.y;
    const float* src; float* dst; int R, C;
    switch (region) {
        case 0: src = fWih;             dst = g_WTenc;          R = 300; C = 256; break;
        case 1: src = bWih;             dst = g_WTenc + 76800;  R = 300; C = 256; break;
        default: src = attW + 200*200;  dst = g_WAT;            R = 400; C = 200; break;
    }
    int total = R * C;
    for (int idx = blockIdx.x * blockDim.x + threadIdx.x; idx < total;
         idx += gridDim.x * blockDim.x) {
        int r = idx / C, c = idx % C;
        dst[c * R + r] = src[r * C + c];
    }
}

// ---------------- K_tab: QL/GL tables ----------------
__global__ void __launch_bounds__(512) k_tab(const float* attInW, const float* decWih,
                                             const float* L_tab) {
    __shared__ float Lt[16][100];
    int tid = threadIdx.x;
    int ib = blockIdx.x * 16;
    for (int i = tid; i < 16 * 100; i += 512) {
        int j = i / 100, k = i % 100;
        Lt[j][k] = (ib + j < 1000) ? L_tab[(ib + j) * 100 + k] : 0.f;
    }
    __syncthreads();
    if (tid < 500) {
        const float* wp = (tid < 200) ? (attInW + tid * 200 + 100)
                                      : (decWih + (tid - 200) * 400 + 100);
        float acc[16];
#pragma unroll
        for (int j = 0; j < 16; j++) acc[j] = 0.f;
        for (int k = 0; k < 100; k++) {
            float wv = wp[k];
#pragma unroll
            for (int j = 0; j < 16; j++) acc[j] += wv * Lt[j][k];
        }
        for (int j = 0; j < 16; j++) {
            if (ib + j < 1000) {
                if (tid < 200) g_QL[(ib + j) * 200 + tid] = acc[j];
                else           g_GL[(ib + j) * 300 + tid - 200] = acc[j];
            }
        }
    }
}

// ---------------- K0: gi precompute ----------------
__global__ void __launch_bounds__(320) k_gi(const int* x, const float* E_tab,
                                            const float* fbih, const float* fbhh,
                                            const float* bbih, const float* bbhh) {
    int dir = blockIdx.y;
    int t0 = blockIdx.x * 16;
    __shared__ int xi[16];
    __shared__ __align__(16) float emb_s[16 * 256];
    int tid = threadIdx.x;
    if (tid < 16) {
        int tg = dir ? (S - 1 - (t0 + tid)) : (t0 + tid);
        xi[tid] = x[tg];
    }
    __syncthreads();
    for (int i = tid; i < 16 * 256; i += 320) {
        int tt = i >> 8, k = i & 255;
        emb_s[i] = E_tab[(size_t)xi[tt] * 256 + k];
    }
    __syncthreads();
    if (tid < 300) {
        int g = tid;
        const float* bih = dir ? bbih : fbih;
        const float* bhh = dir ? bbhh : fbhh;
        float bias = bih[g] + (g < 200 ? bhh[g] : 0.f);
        float acc[16];
#pragma unroll
        for (int tt = 0; tt < 16; tt++) acc[tt] = bias;
        const float* WT = g_WTenc + dir * 256 * 300;
        for (int k4 = 0; k4 < 64; k4++) {
            float w0 = WT[(4 * k4 + 0) * 300 + g];
            float w1 = WT[(4 * k4 + 1) * 300 + g];
            float w2 = WT[(4 * k4 + 2) * 300 + g];
            float w3 = WT[(4 * k4 + 3) * 300 + g];
#pragma unroll
            for (int tt = 0; tt < 16; tt++) {
                float4 e = *reinterpret_cast<const float4*>(emb_s + tt * 256 + 4 * k4);
                acc[tt] += e.x * w0 + e.y * w1 + e.z * w2 + e.w * w3;
            }
        }
        float* Gd = g_G + (size_t)dir * S * 300;
#pragma unroll
        for (int tt = 0; tt < 16; tt++) Gd[(t0 + tt) * 300 + g] = acc[tt];
    }
}

// ---------------- K1: GRU recurrence, 1 barrier/step ----------------
// 320 threads (10 warps). Warp w handles outputs j in [10w, 10w+10).
// Lane = 3*jj + gate (gate 0=r, 1=z, 2=n); lanes 30,31 idle.
// Each lane: full 100-dot with weights in 50 packed-f32x2 regs, h via
// broadcast LDS.128 from a double-buffered h array; gates combined by shfl.
__global__ void __launch_bounds__(320, 1) k_recur(const float* fWhh, const float* bWhh,
                                                  const float* fbhh, const float* bbhh) {
    int dir = blockIdx.x;
    const float* Whh = dir ? bWhh : fWhh;
    const float* bhh = dir ? bbhh : fbhh;
    const float* Gd = g_G + (size_t)dir * S * 300;
    __shared__ __align__(16) float h2[2][112];
    int tid = threadIdx.x;
    int w = tid >> 5, lane = tid & 31;
    int jj = lane / 3, gate = lane % 3;
    int j = w * 10 + jj;               // lanes 30,31: jj=10 -> j in-bounds for weights
    int row = gate * 100 + ((j < 100) ? j : 99);

    unsigned long long wr[50];
    {
        const unsigned long long* wp =
            reinterpret_cast<const unsigned long long*>(Whh + row * 100);
#pragma unroll
        for (int k = 0; k < 50; k++) wr[k] = wp[k];
    }
    bool act = (lane < 30);
    float gr = 0.f, gz = 0.f, gn = 0.f, bhn = 0.f, h_reg = 0.f;
    if (act) {
        if (gate == 0) { gr = Gd[j]; gn = Gd[200 + j]; }
        else if (gate == 1) gz = Gd[100 + j];
        else bhn = bhh[200 + j];
    }
    if (tid < 112) { h2[0][tid] = 0.f; h2[1][tid] = 0.f; }
    __syncthreads();

    float* outbase = g_enc + (dir ? 100 : 0);
    for (int t = 0; t < S; t++) {
        // prefetch G for t+1
        int tn = (t + 1 < S) ? (t + 1) : (S - 1);
        const float* Gp = Gd + tn * 300;
        float ngr = 0.f, ngn = 0.f, ngz = 0.f;
        if (act) {
            if (gate == 0) { ngr = Gp[j]; ngn = Gp[200 + j]; }
            else if (gate == 1) ngz = Gp[100 + j];
        }
        // full 100-dot
        const ulonglong2* hp = reinterpret_cast<const ulonglong2*>(h2[t & 1]);
        unsigned long long a0 = 0ULL, a1 = 0ULL, a2 = 0ULL, a3 = 0ULL;
#pragma unroll
        for (int i = 0; i < 12; i++) {
            ulonglong2 ha = hp[2 * i];
            ulonglong2 hb = hp[2 * i + 1];
            asm("fma.rn.f32x2 %0, %1, %2, %0;" : "+l"(a0) : "l"(wr[4*i]),   "l"(ha.x));
            asm("fma.rn.f32x2 %0, %1, %2, %0;" : "+l"(a1) : "l"(wr[4*i+1]), "l"(ha.y));
            asm("fma.rn.f32x2 %0, %1, %2, %0;" : "+l"(a2) : "l"(wr[4*i+2]), "l"(hb.x));
            asm("fma.rn.f32x2 %0, %1, %2, %0;" : "+l"(a3) : "l"(wr[4*i+3]), "l"(hb.y));
        }
        {
            ulonglong2 hl = hp[24];
            asm("fma.rn.f32x2 %0, %1, %2, %0;" : "+l"(a0) : "l"(wr[48]), "l"(hl.x));
            asm("fma.rn.f32x2 %0, %1, %2, %0;" : "+l"(a1) : "l"(wr[49]), "l"(hl.y));
        }
        asm("add.rn.f32x2 %0, %0, %1;" : "+l"(a0) : "l"(a2));
        asm("add.rn.f32x2 %0, %0, %1;" : "+l"(a1) : "l"(a3));
        asm("add.rn.f32x2 %0, %0, %1;" : "+l"(a0) : "l"(a1));
        float2 f = *reinterpret_cast<float2*>(&a0);
        float dot = f.x + f.y;
        float pre = (gate == 0) ? gr : ((gate == 1) ? gz : bhn);
        float val = dot + pre;
        float v1 = __shfl_sync(0xffffffffu, val, lane + 1);
        float v2 = __shfl_sync(0xffffffffu, val, lane + 2);
        if (act && gate == 0) {
            float rg = sigapx(val);
            float zg = sigapx(v1);
            float ng = tanhapx(gn + rg * v2);
            float hn = ng + zg * (h_reg - ng);
            h_reg = hn;
            h2[(t + 1) & 1][j] = hn;
            int trow = dir ? (S - 1 - t) : t;
            outbase[trow * 200 + j] = hn;
            gr = ngr; gn = ngn;
        } else if (gate == 1) gz = ngz;
        __syncthreads();
    }
}

// ---------------- K2: kp and vp (row-major) ----------------
__global__ void __launch_bounds__(416) k_kv(const float* att_in_b) {
    int i0 = blockIdx.x * 16;
    __shared__ __align__(16) float enc_s[16 * 200];
    int tid = threadIdx.x;
    for (int i = tid; i < 3200; i += 416) enc_s[i] = g_enc[i0 * 200 + i];
    __syncthreads();
    if (tid < 400) {
        int g = tid;
        float bias = att_in_b[200 + g];
        float acc[16];
#pragma unroll
        for (int tt = 0; tt < 16; tt++) acc[tt] = bias;
        for (int k4 = 0; k4 < 50; k4++) {
            float w0 = g_WAT[(4 * k4 + 0) * 400 + g];
            float w1 = g_WAT[(4 * k4 + 1) * 400 + g];
            float w2 = g_WAT[(4 * k4 + 2) * 400 + g];
            float w3 = g_WAT[(4 * k4 + 3) * 400 + g];
#pragma unroll
            for (int tt = 0; tt < 16; tt++) {
                float4 e = *reinterpret_cast<const float4*>(enc_s + tt * 200 + 4 * k4);
                acc[tt] += e.x * w0 + e.y * w1 + e.z * w2 + e.w * w3;
            }
        }
        if (g < 200) {
#pragma unroll
            for (int tt = 0; tt < 16; tt++) g_kp[(i0 + tt) * 200 + g] = acc[tt];
        } else {
            int vg = g - 200;
#pragma unroll
            for (int tt = 0; tt < 16; tt++) g_vp[(i0 + tt) * 200 + vg] = acc[tt];
        }
    }
}

// ---------------- K3: sent, q0, gihd0, flag reset ----------------
__global__ void __launch_bounds__(512) k_sent(const float* mid_W, const float* mid_b,
                                              const float* att_in_W, const float* att_in_b,
                                              const float* decWih) {
    __shared__ float u[200];
    __shared__ float sent_s[100];
    int tid = threadIdx.x;
    for (int i = tid; i < MAXLEN; i += 512) { g_cnt1[i] = 0; g_qflag[i] = 0; }
    if (tid == 0) g_qflag[MAXLEN] = 0;
    if (tid < 100) {
        u[tid] = g_enc[100 + tid];
        u[100 + tid] = g_enc[(S - 1) * 200 + tid];
    }
    __syncthreads();
    if (tid < 100) {
        float acc = mid_b[tid];
#pragma unroll 4
        for (int k = 0; k < 200; k++) acc += mid_W[tid * 200 + k] * u[k];
        sent_s[tid] = acc;
    }
    __syncthreads();
    if (tid < 200) {
        float acc = att_in_b[tid];
#pragma unroll 4
        for (int k = 0; k < 100; k++) acc += att_in_W[tid * 200 + 100 + k] * sent_s[k];
        g_q[tid] = acc;
    }
    if (tid < 300) {
        float acc = 0.f;
#pragma unroll 4
        for (int k = 0; k < 100; k++) acc += decWih[tid * 400 + 100 + k] * sent_s[k];
        g_gihd0[tid] = acc;
    }
}

// ---------------- fused persistent decoder ----------------
struct SAtt {
    float kp[64 * 200];
    float vp[64 * 200];
    float q[200];
    float s[64];
    float e[64];
    float pvp[4 * 200];
    float redM;
};
struct SEpi {
    float pm[64], pz[64], coef[64];
    float part[4 * 200];
    float araw[200];
    float att_s[200];
    float gi[300];
    float gibias[300];
    float dhn[100];
    float bo[200], bq[200];
    float lb_s[1000];
    float hd_s[100];
    float ghd_s[300];
    float wmv[32];
    int   wmi[32];
    float redM, invZ;
    int idx;
};

__global__ void __launch_bounds__(1024, 1) k_dec(
    const float* attOutW, const float* attOutB,
    const float* decWih, const float* dec_bih, const float* dec_bhh,
    const float* lastB, const float* lastW,
    const float* attInW, const float* attInB, float* out) {
    extern __shared__ char sm_raw[];
    int tid = threadIdx.x;
    int b = blockIdx.x;
    int g8 = tid >> 3, s8 = tid & 7;

    if (b < NATT) {
        // ================= attention block =================
        SAtt* sm = (SAtt*)sm_raw;
        int i0 = b * 64;
        for (int i = tid; i < 12800; i += 1024) sm->kp[i] = g_kp[i0 * 200 + i];
        for (int i = tid; i < 12800; i += 1024) sm->vp[i] = g_vp[i0 * 200 + i];
        __syncthreads();
        const float SCALE = 0.07071067811865475f;
        int g16 = tid >> 4, s16 = tid & 15;

        for (int t = 0; t < MAXLEN; t++) {
            if (t > 0) {
                if (tid == 0) while (vld(&g_qflag[t]) == 0u) __nanosleep(20);
                __syncthreads();
            }
            if (tid < 200) sm->q[tid] = __ldcg(&g_q[tid]);
            __syncthreads();
            {
                float acc = 0.f;
#pragma unroll
                for (int jx = 0; jx < 13; jx++) {
                    int k = s16 + 16 * jx;
                    if (k < 200) acc += sm->kp[g16 * 200 + k] * sm->q[k];
                }
                acc += __shfl_xor_sync(0xffffffffu, acc, 8);
                acc = red8(acc);
                if (s16 == 0) sm->s[g16] = acc * SCALE;
            }
            __syncthreads();
            if (tid < 32) {
                float m = warp_max(fmaxf(sm->s[tid], sm->s[tid + 32]));
                if (tid == 0) sm->redM = m;
            }
            __syncthreads();
            if (tid < 64) sm->e[tid] = __expf(sm->s[tid] - sm->redM);
            __syncthreads();
            if (tid < 32) {
                float z = warp_sum(sm->e[tid] + sm->e[tid + 32]);
                if (tid == 0) { __stcg(&g_pm[b], sm->redM); __stcg(&g_pz[b], z); }
            }
            if (tid < 800) {
                int g = tid % 200, ip = tid / 200;
                float a = 0.f;
#pragma unroll
                for (int jx = 0; jx < 16; jx++) {
                    int i2 = ip * 16 + jx;
                    a += sm->e[i2] * sm->vp[i2 * 200 + g];
                }
                sm->pvp[ip * 200 + g] = a;
            }
            __syncthreads();
            if (tid < 200) {
                float a = sm->pvp[tid] + sm->pvp[200 + tid] + sm->pvp[400 + tid] +
                          sm->pvp[600 + tid];
                __stcg(&g_pv[b * 200 + tid], a);
            }
            __threadfence();
            __syncthreads();
            if (tid == 0) atomicAdd(&g_cnt1[t], 1u);
            __syncthreads();
        }
    } else {
        // ================= epilogue block (does everything serial) ==========
        SEpi* sm = (SEpi*)sm_raw;
        for (int i = tid; i < 300; i += 1024) {
            sm->gibias[i] = dec_bih[i] + (i < 200 ? dec_bhh[i] : 0.f);
            sm->ghd_s[i] = g_gihd0[i];
        }
        for (int i = tid; i < 100; i += 1024) sm->dhn[i] = dec_bhh[200 + i];
        for (int i = tid; i < 200; i += 1024) {
            sm->bo[i] = attOutB[i];
            sm->bq[i] = attInB[i];
        }
        for (int i = tid; i < 1000; i += 1024) sm->lb_s[i] = lastB[i];
        __syncthreads();

        for (int t = 0; t < MAXLEN; t++) {
            if (tid == 0) while (vld(&g_cnt1[t]) < NATT) __nanosleep(20);
            __syncthreads();
            if (tid < 64) sm->pm[tid] = __ldcg(&g_pm[tid]);
            else if (tid < 128) sm->pz[tid - 64] = __ldcg(&g_pz[tid - 64]);
            __syncthreads();
            if (tid < 32) {
                float m = warp_max(fmaxf(sm->pm[tid], sm->pm[tid + 32]));
                if (tid == 0) sm->redM = m;
            }
            __syncthreads();
            if (tid < 64) sm->coef[tid] = __expf(sm->pm[tid] - sm->redM);
            __syncthreads();
            if (tid < 32) {
                float z = warp_sum(sm->coef[tid] * sm->pz[tid] +
                                   sm->coef[tid + 32] * sm->pz[tid + 32]);
                if (tid == 0) sm->invZ = __fdividef(1.f, z);
            }
            __syncthreads();
            if (tid < 800) {
                int g = tid % 200, ip = tid / 200;
                float a = 0.f;
#pragma unroll
                for (int jx = 0; jx < 16; jx++) {
                    int bb = ip * 16 + jx;
                    a += sm->coef[bb] * __ldcg(&g_pv[bb * 200 + g]);
                }
                sm->part[ip * 200 + g] = a;
            }
            __syncthreads();
            if (tid < 200)
                sm->araw[tid] = (sm->part[tid] + sm->part[200 + tid] +
                                 sm->part[400 + tid] + sm->part[600 + tid]) * sm->invZ;
            __syncthreads();
            // att projection: 8 lanes/row, rows 0..199
            for (int r = g8; r < 200; r += 128) {
                float a = 0.f;
#pragma unroll
                for (int jx = 0; jx < 25; jx++) {
                    int k = s8 + 8 * jx;
                    a += attOutW[r * 200 + k] * sm->araw[k];
                }
                a = red8(a);
                if (s8 == 0) sm->att_s[r] = a + sm->bo[r];
            }
            __syncthreads();
            // gi(att part): dec_Wih[:, 200:400] @ att_s
            for (int r = g8; r < 300; r += 128) {
                float a = 0.f;
#pragma unroll
                for (int jx = 0; jx < 25; jx++) {
                    int k = s8 + 8 * jx;
                    a += decWih[r * 400 + 200 + k] * sm->att_s[k];
                }
                a = red8(a);
                if (s8 == 0) sm->gi[r] = a;
            }
            __syncthreads();
            if (tid < 100) {
                float ar = sm->gi[tid] + sm->ghd_s[tid] + sm->gibias[tid];
                float az = sm->gi[100 + tid] + sm->ghd_s[100 + tid] + sm->gibias[100 + tid];
                float an = sm->gi[200 + tid] + sm->ghd_s[200 + tid] + sm->gibias[200 + tid];
                float r_ = sigapx(ar);
                float z_ = sigapx(az);
                float n_ = tanhapx(an + r_ * sm->dhn[tid]);
                sm->hd_s[tid] = (1.f - z_) * n_;
            }
            __syncthreads();
            // scores = lastW @ hd + lastB : 8 lanes/row, 8 passes; argmax
            float bv = -3.4e38f; int bi = 0x7fffffff;
#pragma unroll
            for (int p = 0; p < 8; p++) {
                int r = g8 + 128 * p;
                if (r < 1000) {
                    float a = 0.f;
#pragma unroll
                    for (int jx = 0; jx < 13; jx++) {
                        int k = s8 + 8 * jx;
                        if (k < 100) a += lastW[r * 100 + k] * sm->hd_s[k];
                    }
                    a = red8(a);
                    if (s8 == 0) {
                        float sc = a + sm->lb_s[r];
                        out[t * 1000 + r] = sc;
                        if (sc > bv || (sc == bv && r < bi)) { bv = sc; bi = r; }
                    }
                }
            }
#pragma unroll
            for (int o = 16; o; o >>= 1) {
                float ov = __shfl_xor_sync(0xffffffffu, bv, o);
                int oi = __shfl_xor_sync(0xffffffffu, bi, o);
                if (ov > bv || (ov == bv && oi < bi)) { bv = ov; bi = oi; }
            }
            if ((tid & 31) == 0) { sm->wmv[tid >> 5] = bv; sm->wmi[tid >> 5] = bi; }
            __syncthreads();
            if (tid < 32) {
                float v = sm->wmv[tid]; int ix = sm->wmi[tid];
#pragma unroll
                for (int o = 16; o; o >>= 1) {
                    float ov = __shfl_xor_sync(0xffffffffu, v, o);
                    int oi = __shfl_xor_sync(0xffffffffu, ix, o);
                    if (ov > v || (ov == v && oi < ix)) { v = ov; ix = oi; }
                }
                if (tid == 0) sm->idx = ix;
            }
            __syncthreads();
            int idx = sm->idx;
            // q = Wq[:, :100] @ hd + QL[idx] + bq  (rows 0..199)
            for (int r = g8; r < 200; r += 128) {
                float a = 0.f;
#pragma unroll
                for (int jx = 0; jx < 13; jx++) {
                    int k = s8 + 8 * jx;
                    if (k < 100) a += attInW[r * 200 + k] * sm->hd_s[k];
                }
                a = red8(a);
                if (s8 == 0)
                    __stcg(&g_q[r], a + __ldcg(&g_QL[idx * 200 + r]) + sm->bq[r]);
            }
            __threadfence();
            __syncthreads();
            if (tid == 0) *(volatile unsigned*)&g_qflag[t + 1] = 1u;
            // ghd for next step (overlaps with attention blocks)
            for (int r = g8; r < 300; r += 128) {
                float a = 0.f;
#pragma unroll
                for (int jx = 0; jx < 13; jx++) {
                    int k = s8 + 8 * jx;
                    if (k < 100) a += decWih[r * 400 + k] * sm->hd_s[k];
                }
                a = red8(a);
                if (s8 == 0) sm->ghd_s[r] = a + __ldcg(&g_GL[idx * 300 + r]);
            }
            __syncthreads();
        }
    }
}

// ---------------- host launcher ----------------
extern "C" void kernel_launch(void* const* d_in, const int* in_sizes, int n_in,
                              void* d_out, int out_size) {
    const int*   x         = (const int*)  d_in[0];
    const float* E_tab     = (const float*)d_in[1];
    const float* L_tab     = (const float*)d_in[2];
    const float* enc_f_Wih = (const float*)d_in[3];
    const float* enc_f_Whh = (const float*)d_in[4];
    const float* enc_f_bih = (const float*)d_in[5];
    const float* enc_f_bhh = (const float*)d_in[6];
    const float* enc_b_Wih = (const float*)d_in[7];
    const float* enc_b_Whh = (const float*)d_in[8];
    const float* enc_b_bih = (const float*)d_in[9];
    const float* enc_b_bhh = (const float*)d_in[10];
    const float* mid_W     = (const float*)d_in[11];
    const float* mid_b     = (const float*)d_in[12];
    const float* dec_Wih   = (const float*)d_in[15];
    const float* dec_bih   = (const float*)d_in[17];
    const float* dec_bhh   = (const float*)d_in[18];
    const float* last_W    = (const float*)d_in[19];
    const float* last_b    = (const float*)d_in[20];
    const float* att_in_W  = (const float*)d_in[21];
    const float* att_in_b  = (const float*)d_in[22];
    const float* att_out_W = (const float*)d_in[23];
    const float* att_out_b = (const float*)d_in[24];
    float* out = (float*)d_out;

    static int smem_set = 0;
    int dec_smem = (int)sizeof(SAtt);
    if (dec_smem < (int)sizeof(SEpi)) dec_smem = (int)sizeof(SEpi);
    if (!smem_set) {
        cudaFuncSetAttribute(k_dec, cudaFuncAttributeMaxDynamicSharedMemorySize,
                             dec_smem);
        smem_set = 1;
    }

    k_transp<<<dim3(80, 3), 256>>>(enc_f_Wih, enc_b_Wih, att_in_W);
    k_tab<<<63, 512>>>(att_in_W, dec_Wih, L_tab);
    k_gi<<<dim3(S / 16, 2), 320>>>(x, E_tab, enc_f_bih, enc_f_bhh, enc_b_bih, enc_b_bhh);
    k_recur<<<2, 320>>>(enc_f_Whh, enc_b_Whh, enc_f_bhh, enc_b_bhh);
    k_kv<<<S / 16, 416>>>(att_in_b);
    k_sent<<<1, 512>>>(mid_W, mid_b, att_in_W, att_in_b, dec_Wih);
    k_dec<<<NATT + 1, 1024, dec_smem>>>(att_out_W, att_out_b, dec_Wih, dec_bih,
                                        dec_bhh, last_b, last_W, att_in_W, att_in_b,
                                        out);
}